// round 11
// baseline (speedup 1.0000x reference)
#include <cuda_runtime.h>
#include <cuda_bf16.h>
#include <cstdint>

// Problem constants (fixed shapes from reference)
constexpr int B = 256;
constexpr int P = 1024;
constexpr int G = 128;
constexpr float DIST_T2 = 500.0f * 500.0f;   // compare squared distance
constexpr float BBOX_THRESH = 0.1f;
constexpr float SENTINEL = 1.0e15f;          // d2 ~ 3e30: finite, never ties/beats real

// One-warp CTAs: 8192 CTAs vs ~4736 resident (32 CTA/SM hw cap) -> the
// GigaThread engine backfills finished warps per-SMSP, erasing the static
// per-SMSP load-imbalance tail (issue was pinned at ~1/1.4).
constexpr int THREADS = 32;
constexpr int PROPS_PER_CTA = 32;
constexpr int CHUNKS_PB = P / PROPS_PER_CTA;  // 32

__device__ __forceinline__ uint64_t pack2(float lo, float hi) {
    uint64_t r;
    asm("mov.b64 %0, {%1, %2};" : "=l"(r) : "f"(lo), "f"(hi));
    return r;
}

// d2 for a GT pair, entirely inside one asm block so the packed temporaries
// never leak into C++ register allocation. Inputs pre-negated: d = p + (-g).
__device__ __forceinline__ void d2pair(uint64_t X2, uint64_t Y2, uint64_t Z2,
                                       uint64_t gnx, uint64_t gny, uint64_t gnz,
                                       float& a, float& b) {
    asm("{\n\t"
        ".reg .b64 dx, dy, dz, acc;\n\t"
        "add.rn.f32x2 dx, %2, %4;\n\t"
        "add.rn.f32x2 dy, %3, %5;\n\t"
        "add.rn.f32x2 dz, %6, %7;\n\t"
        "mul.rn.f32x2 acc, dz, dz;\n\t"
        "fma.rn.f32x2 acc, dy, dy, acc;\n\t"
        "fma.rn.f32x2 acc, dx, dx, acc;\n\t"
        "mov.b64 {%0, %1}, acc;\n\t"
        "}"
        : "=f"(a), "=f"(b)
        : "l"(X2), "l"(Y2), "l"(gnx), "l"(gny), "l"(Z2), "l"(gnz));
}

__global__ __launch_bounds__(THREADS) void proposal_kernel(
    const float* __restrict__ topk_index,    // [B,P,3]
    const float* __restrict__ topk_confs,    // [B,P]
    const float* __restrict__ bbox_preds,    // [B,P,2]
    const float* __restrict__ gt_3d,         // [B,G,3]
    const float* __restrict__ gt_bbox,       // [B,G,2]
    const int*   __restrict__ num_person,    // [B]
    float*       __restrict__ out)           // [B,P,7]
{
    // Dense pair layout -> 3 x LDS.128 per 2 pairs (4 GT points):
    //   sxy[i] = ( (-gx_{2i},-gx_{2i+1}), (-gy_{2i},-gy_{2i+1}) )
    //   szz[k] = ( (-gz_{4k},-gz_{4k+1}), (-gz_{4k+2},-gz_{4k+3}) )
    __shared__ ulonglong2 sxy[G / 2];     // 1024 B
    __shared__ ulonglong2 szz[G / 4];     //  512 B

    const int tid   = threadIdx.x;
    const int blk   = blockIdx.x;
    const int b     = blk >> 5;           // 32 chunks per batch
    const int chunk = blk & 31;
    const int n     = num_person[b];      // uniform per warp

    // Stage GT negated. Each thread loads 4 consecutive GT points (12
    // contiguous floats = 3 x LDG.128; 48B stride keeps 16B alignment) and
    // scatters into the packed-pair layout. Slots g >= n get the sentinel so
    // the padded, remainder-free loop is exact: real slots come first
    // (n >= 1), max real d2 ~ 1.92e8 << sentinel d2 ~ 3e30.
    {
        const float4* g4 =
            reinterpret_cast<const float4*>(gt_3d + ((size_t)b * G + tid * 4) * 3);
        const float4 v0 = g4[0];   // x0 y0 z0 x1
        const float4 v1 = g4[1];   // y1 z1 x2 y2
        const float4 v2 = g4[2];   // z2 x3 y3 z3

        const float gx[4] = { v0.x, v0.w, v1.z, v2.y };
        const float gy[4] = { v0.y, v1.x, v1.w, v2.z };
        const float gz[4] = { v0.z, v1.y, v2.x, v2.w };

        float* fxy = reinterpret_cast<float*>(sxy);
        float* fzz = reinterpret_cast<float*>(szz);
        #pragma unroll
        for (int j = 0; j < 4; ++j) {
            const int g = tid * 4 + j;
            const bool valid = (g < n);
            const float ngx = valid ? -gx[j] : -SENTINEL;
            const float ngy = valid ? -gy[j] : -SENTINEL;
            const float ngz = valid ? -gz[j] : -SENTINEL;
            fxy[(g >> 1) * 4 + (g & 1)]     = ngx;   // x lane of pair g>>1
            fxy[(g >> 1) * 4 + 2 + (g & 1)] = ngy;   // y lane
            fzz[g]                          = ngz;   // z lanes, 4 per record
        }
    }
    __syncwarp();

    const int    p  = chunk * PROPS_PER_CTA + tid;
    const size_t bp = (size_t)b * P + p;

    const float x = topk_index[bp * 3 + 0];
    const float y = topk_index[bp * 3 + 1];
    const float z = topk_index[bp * 3 + 2];

    // Hoist per-proposal gmem loads so their latency overlaps the loop.
    const float q0 = bbox_preds[bp * 2 + 0];
    const float q1 = bbox_preds[bp * 2 + 1];
    const float cf = topk_confs[bp];

    const uint64_t X2 = pack2(x, x);
    const uint64_t Y2 = pack2(y, y);
    const uint64_t Z2 = pack2(z, z);

    // 4 champions, one per residue class g mod 4 (short carried chains).
    // Strict < keeps first-index-within-residue semantics.
    float b0 = 3.402823466e38f, b1 = 3.402823466e38f;
    float b2 = 3.402823466e38f, b3 = 3.402823466e38f;
    int   i0 = 0, i1 = 0, i2 = 0, i3 = 0;

    const int nsteps = ((n + 7) & ~7) >> 2;   // 4 GT per step, no remainder
    #pragma unroll 2
    for (int k = 0; k < nsteps; ++k) {
        const ulonglong2 A0 = sxy[2 * k];      // pairs 2k   : LDS.128
        const ulonglong2 A1 = sxy[2 * k + 1];  // pairs 2k+1 : LDS.128
        const ulonglong2 Zk = szz[k];          // both z-pairs: LDS.128

        float d0a, d0b, d1a, d1b;
        d2pair(X2, Y2, Z2, A0.x, A0.y, Zk.x, d0a, d0b);  // g = 4k, 4k+1
        d2pair(X2, Y2, Z2, A1.x, A1.y, Zk.y, d1a, d1b);  // g = 4k+2, 4k+3

        if (d0a < b0) { b0 = d0a; i0 = k; }
        if (d0b < b1) { b1 = d0b; i1 = k; }
        if (d1a < b2) { b2 = d1a; i2 = k; }
        if (d1b < b3) { b3 = d1b; i3 = k; }
    }

    // Exact first-index merge: lexicographic (d2, global index).
    int   g0 = 4 * i0, g1 = 4 * i1 + 1, g2 = 4 * i2 + 2, g3 = 4 * i3 + 3;
    float ba = b0; int ga = g0;
    if ((b1 < ba) || (b1 == ba && g1 < ga)) { ba = b1; ga = g1; }
    if ((b2 < ba) || (b2 == ba && g2 < ga)) { ba = b2; ga = g2; }
    if ((b3 < ba) || (b3 == ba && g3 < ga)) { ba = b3; ga = g3; }

    // dist > 500  <=>  d2 > 500^2 (sqrt monotone; compare-exact)
    const float p2g = (ba > DIST_T2) ? -1.0f : (float)ga;

    // Matched GT bbox: one divergent LDG.64 at the end (no smem staging).
    const float2 mb = reinterpret_cast<const float2*>(gt_bbox)[(size_t)b * G + ga];
    const bool cond = (p2g >= 0.0f) &&
                      ((q0 < mb.x - BBOX_THRESH) || (q1 < mb.y - BBOX_THRESH));

    // 32 threads x 7 contiguous floats: 896B contiguous per warp.
    float* o = out + bp * 7;
    o[0] = x;  o[1] = y;  o[2] = z;
    o[3] = p2g; o[4] = cf;
    o[5] = cond ? mb.x : q0;
    o[6] = cond ? mb.y : q1;
}

extern "C" void kernel_launch(void* const* d_in, const int* in_sizes, int n_in,
                              void* d_out, int out_size) {
    const float* topk_index  = (const float*)d_in[0];  // [B,P,3]
    const float* topk_confs  = (const float*)d_in[1];  // [B,P]
    const float* bbox_preds  = (const float*)d_in[2];  // [B,P,2]
    const float* gt_3d       = (const float*)d_in[3];  // [B,G,3]
    const float* gt_bbox     = (const float*)d_in[4];  // [B,G,2]
    const int*   num_person  = (const int*)  d_in[5];  // [B]
    float*       out         = (float*)d_out;          // [B,P,7]

    proposal_kernel<<<B * CHUNKS_PB, THREADS>>>(topk_index, topk_confs, bbox_preds,
                                                gt_3d, gt_bbox, num_person, out);
}

// round 12
// speedup vs baseline: 1.1775x; 1.1775x over previous
#include <cuda_runtime.h>
#include <cuda_bf16.h>
#include <cstdint>

// Problem constants (fixed shapes from reference)
constexpr int B = 256;
constexpr int P = 1024;
constexpr int G = 128;
constexpr float DIST_T2 = 500.0f * 500.0f;   // compare squared distance
constexpr float BBOX_THRESH = 0.1f;
constexpr float SENTINEL = 1.0e15f;          // d2 ~ 3e30: finite, never ties/beats real

constexpr int THREADS = 128;                  // 1 proposal/thread
constexpr int PROPS_PER_CTA = THREADS;        // 128
constexpr int CHUNKS_PB = P / PROPS_PER_CTA;  // 8

__device__ __forceinline__ uint64_t pack2(float lo, float hi) {
    uint64_t r;
    asm("mov.b64 %0, {%1, %2};" : "=l"(r) : "f"(lo), "f"(hi));
    return r;
}

// d2 for a GT pair, entirely inside one asm block so the packed temporaries
// never leak into C++ register allocation. Inputs pre-negated: d = p + (-g).
__device__ __forceinline__ void d2pair(uint64_t X2, uint64_t Y2, uint64_t Z2,
                                       uint64_t gnx, uint64_t gny, uint64_t gnz,
                                       float& a, float& b) {
    asm("{\n\t"
        ".reg .b64 dx, dy, dz, acc;\n\t"
        "add.rn.f32x2 dx, %2, %4;\n\t"
        "add.rn.f32x2 dy, %3, %5;\n\t"
        "add.rn.f32x2 dz, %6, %7;\n\t"
        "mul.rn.f32x2 acc, dz, dz;\n\t"
        "fma.rn.f32x2 acc, dy, dy, acc;\n\t"
        "fma.rn.f32x2 acc, dx, dx, acc;\n\t"
        "mov.b64 {%0, %1}, acc;\n\t"
        "}"
        : "=f"(a), "=f"(b)
        : "l"(X2), "l"(Y2), "l"(gnx), "l"(gny), "l"(Z2), "l"(gnz));
}

__global__ __launch_bounds__(THREADS) void proposal_kernel(
    const float* __restrict__ topk_index,    // [B,P,3]
    const float* __restrict__ topk_confs,    // [B,P]
    const float* __restrict__ bbox_preds,    // [B,P,2]
    const float* __restrict__ gt_3d,         // [B,G,3]
    const float* __restrict__ gt_bbox,       // [B,G,2]
    const int*   __restrict__ num_person,    // [B]
    float*       __restrict__ out)           // [B,P,7]
{
    // Dense pair layout -> 3 x LDS.128 per 2 pairs (4 GT points):
    //   sxy[i] = ( (-gx_{2i},-gx_{2i+1}), (-gy_{2i},-gy_{2i+1}) )
    //   szz[k] = ( (-gz_{4k},-gz_{4k+1}), (-gz_{4k+2},-gz_{4k+3}) )
    __shared__ ulonglong2 sxy[G / 2];
    __shared__ ulonglong2 szz[G / 4];

    const int tid   = threadIdx.x;
    const int b     = blockIdx.x >> 3;        // 8 chunks per batch
    const int chunk = blockIdx.x & 7;
    const int n     = num_person[b];          // uniform per CTA

    // Stage GT negated (tid == g). Slots g >= n get the sentinel so the
    // padded, remainder-free loop is exact: real slots come first (n >= 1),
    // max real d2 ~ 1.92e8 << sentinel d2 ~ 3e30 (never ties, never wins).
    {
        float ngx = -SENTINEL, ngy = -SENTINEL, ngz = -SENTINEL;
        if (tid < n) {
            const float* g3 = gt_3d + ((size_t)b * G + tid) * 3;
            ngx = -g3[0]; ngy = -g3[1]; ngz = -g3[2];
        }
        float* fxy = reinterpret_cast<float*>(sxy);
        fxy[(tid >> 1) * 4 + (tid & 1)]     = ngx;   // x lane of pair tid>>1
        fxy[(tid >> 1) * 4 + 2 + (tid & 1)] = ngy;   // y lane
        reinterpret_cast<float*>(szz)[tid]  = ngz;   // z lanes, 4 per record
    }
    __syncthreads();

    const int    p  = chunk * PROPS_PER_CTA + tid;
    const size_t bp = (size_t)b * P + p;

    const float x = topk_index[bp * 3 + 0];
    const float y = topk_index[bp * 3 + 1];
    const float z = topk_index[bp * 3 + 2];

    // Hoist per-proposal gmem loads so their latency overlaps the loop.
    const float q0 = bbox_preds[bp * 2 + 0];
    const float q1 = bbox_preds[bp * 2 + 1];
    const float cf = topk_confs[bp];

    const uint64_t X2 = pack2(x, x);
    const uint64_t Y2 = pack2(y, y);
    const uint64_t Z2 = pack2(z, z);

    // 4 champions, one per residue class g mod 4. Update uses
    // FSETP (off-chain) + FMNMX + SEL: loop-carried deps are only the 4-cycle
    // FMNMX (best) and SEL (idx), not a 13-cycle pred-guard chain.
    float b0 = 3.402823466e38f, b1 = 3.402823466e38f;
    float b2 = 3.402823466e38f, b3 = 3.402823466e38f;
    int   i0 = 0, i1 = 0, i2 = 0, i3 = 0;

    const int nsteps = ((n + 7) & ~7) >> 2;   // 4 GT per step, no remainder
    #pragma unroll 2
    for (int k = 0; k < nsteps; ++k) {
        const ulonglong2 A0 = sxy[2 * k];      // pairs 2k   : LDS.128
        const ulonglong2 A1 = sxy[2 * k + 1];  // pairs 2k+1 : LDS.128
        const ulonglong2 Zk = szz[k];          // both z-pairs: LDS.128

        float d0a, d0b, d1a, d1b;
        d2pair(X2, Y2, Z2, A0.x, A0.y, Zk.x, d0a, d0b);  // g = 4k, 4k+1
        d2pair(X2, Y2, Z2, A1.x, A1.y, Zk.y, d1a, d1b);  // g = 4k+2, 4k+3

        const bool c0 = d0a < b0;
        const bool c1 = d0b < b1;
        const bool c2 = d1a < b2;
        const bool c3 = d1b < b3;
        b0 = fminf(b0, d0a);  i0 = c0 ? k : i0;
        b1 = fminf(b1, d0b);  i1 = c1 ? k : i1;
        b2 = fminf(b2, d1a);  i2 = c2 ? k : i2;
        b3 = fminf(b3, d1b);  i3 = c3 ? k : i3;
    }

    // Exact first-index merge: lexicographic (d2, global index). Strict <
    // within each residue plus index tie-break across residues reproduces
    // JAX argmin's first-index semantics exactly.
    int   g0 = 4 * i0, g1 = 4 * i1 + 1, g2 = 4 * i2 + 2, g3 = 4 * i3 + 3;
    float ba = b0; int ga = g0;
    if ((b1 < ba) || (b1 == ba && g1 < ga)) { ba = b1; ga = g1; }
    if ((b2 < ba) || (b2 == ba && g2 < ga)) { ba = b2; ga = g2; }
    if ((b3 < ba) || (b3 == ba && g3 < ga)) { ba = b3; ga = g3; }

    // dist > 500  <=>  d2 > 500^2 (sqrt monotone; compare-exact)
    const float p2g = (ba > DIST_T2) ? -1.0f : (float)ga;

    // Matched GT bbox: one divergent LDG.64 (L2-hot), no smem staging.
    const float2 mb = reinterpret_cast<const float2*>(gt_bbox)[(size_t)b * G + ga];
    const bool cond = (p2g >= 0.0f) &&
                      ((q0 < mb.x - BBOX_THRESH) || (q1 < mb.y - BBOX_THRESH));

    // Direct 7-float store (contiguous 28B per thread, 3.5KB per CTA tile).
    float* o = out + bp * 7;
    o[0] = x;  o[1] = y;  o[2] = z;
    o[3] = p2g; o[4] = cf;
    o[5] = cond ? mb.x : q0;
    o[6] = cond ? mb.y : q1;
}

extern "C" void kernel_launch(void* const* d_in, const int* in_sizes, int n_in,
                              void* d_out, int out_size) {
    const float* topk_index  = (const float*)d_in[0];  // [B,P,3]
    const float* topk_confs  = (const float*)d_in[1];  // [B,P]
    const float* bbox_preds  = (const float*)d_in[2];  // [B,P,2]
    const float* gt_3d       = (const float*)d_in[3];  // [B,G,3]
    const float* gt_bbox     = (const float*)d_in[4];  // [B,G,2]
    const int*   num_person  = (const int*)  d_in[5];  // [B]
    float*       out         = (float*)d_out;          // [B,P,7]

    proposal_kernel<<<B * CHUNKS_PB, THREADS>>>(topk_index, topk_confs, bbox_preds,
                                                gt_3d, gt_bbox, num_person, out);
}